// round 1
// baseline (speedup 1.0000x reference)
#include <cuda_runtime.h>
#include <cstdint>

// ---------------------------------------------------------------------------
// EdgeRolandGNN: preprocess MLP (2x GEMM+leaky) -> GCN1 -> blend -> GCN2 ->
// blend -> edge scoring.  All fp32.
// ---------------------------------------------------------------------------

#define LSLOPE 0.01f

static constexpr int MAXN = 50000;

// Scratch (device globals; no allocation allowed)
__device__ float g_h0 [MAXN * 256];   // after MLP layer 1
__device__ float g_h1 [MAXN * 128];   // after MLP layer 2
__device__ float g_xw1[MAXN * 128];   // h1 @ W_c1
__device__ float g_agg1[MAXN * 128];
__device__ float g_xw2[MAXN * 64];    // emb1 @ W_c2
__device__ float g_agg2[MAXN * 64];
__device__ float g_dis [MAXN];
__device__ int   g_deg [MAXN];
__device__ float g_wsum[64];
__device__ float g_bsum[1];

// ---------------------------------------------------------------------------
// init: zero deg + agg buffers
// ---------------------------------------------------------------------------
__global__ void init_kernel(int N) {
    int idx = blockIdx.x * blockDim.x + threadIdx.x;
    int n128 = N * 128;
    int n64  = N * 64;
    if (idx < n128) g_agg1[idx] = 0.0f;
    if (idx < n64)  g_agg2[idx] = 0.0f;
    if (idx < N)    g_deg[idx]  = 0;
}

// ---------------------------------------------------------------------------
// degree histogram over dst, then dis = rsqrt(deg+1)
// ---------------------------------------------------------------------------
__global__ void deg_kernel(const int* __restrict__ dst, int E) {
    int e = blockIdx.x * blockDim.x + threadIdx.x;
    if (e < E) atomicAdd(&g_deg[dst[e]], 1);
}

__global__ void dis_kernel(int N) {
    int i = blockIdx.x * blockDim.x + threadIdx.x;
    if (i < N) g_dis[i] = rsqrtf((float)g_deg[i] + 1.0f);
}

// ---------------------------------------------------------------------------
// wsum = W_post[:,0]+W_post[:,1]  (W_post is [64,2] row-major), bsum = b0+b1
// ---------------------------------------------------------------------------
__global__ void wsum_kernel(const float* __restrict__ W_post,
                            const float* __restrict__ b_post) {
    int i = threadIdx.x;
    if (i < 64) g_wsum[i] = W_post[2 * i] + W_post[2 * i + 1];
    if (i == 0) g_bsum[0] = b_post[0] + b_post[1];
}

// ---------------------------------------------------------------------------
// Tiled fp32 GEMM:  C[M,N] = act(A[M,K] @ B[K,N] + bias)
// BM=128, BN=64, BK=16, 256 threads, thread tile 8x4.
// Requires: K % 16 == 0, N % 64 == 0 (true for all 4 GEMMs here).
// ---------------------------------------------------------------------------
template <bool BIAS, bool ACT>
__global__ __launch_bounds__(256)
void gemm_kernel(const float* __restrict__ A, const float* __restrict__ B,
                 const float* __restrict__ bias, float* __restrict__ C,
                 int M, int N, int K) {
    constexpr int BM = 128, BN = 64, BK = 16, TM = 8, TN = 4;
    __shared__ float As[BK][BM + 4];   // pad to break bank conflicts on store
    __shared__ float Bs[BK][BN];

    const int tid  = threadIdx.x;
    const int bm   = blockIdx.y * BM;
    const int bn   = blockIdx.x * BN;
    const int tcol = tid & 15;    // 0..15 -> cols tcol*TN .. +3
    const int trow = tid >> 4;    // 0..15 -> rows trow*TM .. +7

    float acc[TM][TN];
#pragma unroll
    for (int m = 0; m < TM; m++)
#pragma unroll
        for (int n = 0; n < TN; n++) acc[m][n] = 0.0f;

    for (int k0 = 0; k0 < K; k0 += BK) {
        // load A tile: 128x16 = 512 float4, 2 per thread, transpose into As
#pragma unroll
        for (int i = 0; i < 2; i++) {
            int idx = tid + i * 256;
            int r   = idx >> 2;
            int c   = (idx & 3) << 2;
            float4 v = make_float4(0.f, 0.f, 0.f, 0.f);
            int gr = bm + r;
            if (gr < M)
                v = *reinterpret_cast<const float4*>(&A[(size_t)gr * K + k0 + c]);
            As[c + 0][r] = v.x;
            As[c + 1][r] = v.y;
            As[c + 2][r] = v.z;
            As[c + 3][r] = v.w;
        }
        // load B tile: 16x64 = 256 float4, 1 per thread
        {
            int r = tid >> 4;
            int c = (tid & 15) << 2;
            *reinterpret_cast<float4*>(&Bs[r][c]) =
                *reinterpret_cast<const float4*>(&B[(size_t)(k0 + r) * N + bn + c]);
        }
        __syncthreads();

#pragma unroll
        for (int kk = 0; kk < BK; kk++) {
            float4 a0 = *reinterpret_cast<const float4*>(&As[kk][trow * TM]);
            float4 a1 = *reinterpret_cast<const float4*>(&As[kk][trow * TM + 4]);
            float4 bv = *reinterpret_cast<const float4*>(&Bs[kk][tcol * TN]);
            float a[TM] = {a0.x, a0.y, a0.z, a0.w, a1.x, a1.y, a1.z, a1.w};
            float b[TN] = {bv.x, bv.y, bv.z, bv.w};
#pragma unroll
            for (int m = 0; m < TM; m++)
#pragma unroll
                for (int n = 0; n < TN; n++) acc[m][n] = fmaf(a[m], b[n], acc[m][n]);
        }
        __syncthreads();
    }

    float4 bvec = make_float4(0.f, 0.f, 0.f, 0.f);
    if (BIAS)
        bvec = *reinterpret_cast<const float4*>(&bias[bn + tcol * TN]);

#pragma unroll
    for (int m = 0; m < TM; m++) {
        int gr = bm + trow * TM + m;
        if (gr < M) {
            float4 o;
            o.x = acc[m][0] + bvec.x;
            o.y = acc[m][1] + bvec.y;
            o.z = acc[m][2] + bvec.z;
            o.w = acc[m][3] + bvec.w;
            if (ACT) {
                o.x = (o.x >= 0.f) ? o.x : LSLOPE * o.x;
                o.y = (o.y >= 0.f) ? o.y : LSLOPE * o.y;
                o.z = (o.z >= 0.f) ? o.z : LSLOPE * o.z;
                o.w = (o.w >= 0.f) ? o.w : LSLOPE * o.w;
            }
            *reinterpret_cast<float4*>(&C[(size_t)gr * N + bn + tcol * TN]) = o;
        }
    }
}

// ---------------------------------------------------------------------------
// Edge scatter: agg[dst] += xw[src] * dis[src]*dis[dst], via red.global.v4.f32
// H=128: warp per edge.  H=64: 16 lanes per edge.
// ---------------------------------------------------------------------------
__device__ __forceinline__ void red_add_v4(float* p, float4 v) {
    unsigned long long a = (unsigned long long)__cvta_generic_to_global(p);
    asm volatile("red.global.add.v4.f32 [%0], {%1, %2, %3, %4};"
                 :: "l"(a), "f"(v.x), "f"(v.y), "f"(v.z), "f"(v.w)
                 : "memory");
}

__global__ void scatter128_kernel(const int* __restrict__ src,
                                  const int* __restrict__ dst,
                                  const float* __restrict__ xw, int E) {
    int gid  = blockIdx.x * blockDim.x + threadIdx.x;
    int e    = gid >> 5;
    if (e >= E) return;
    int lane = gid & 31;
    int s = __ldg(&src[e]);
    int d = __ldg(&dst[e]);
    float c = g_dis[s] * g_dis[d];
    float4 v = *reinterpret_cast<const float4*>(&xw[(size_t)s * 128 + lane * 4]);
    v.x *= c; v.y *= c; v.z *= c; v.w *= c;
    red_add_v4(&g_agg1[(size_t)d * 128 + lane * 4], v);
}

__global__ void scatter64_kernel(const int* __restrict__ src,
                                 const int* __restrict__ dst,
                                 const float* __restrict__ xw, int E) {
    int gid  = blockIdx.x * blockDim.x + threadIdx.x;
    int e    = gid >> 4;
    if (e >= E) return;
    int lane = gid & 15;
    int s = __ldg(&src[e]);
    int d = __ldg(&dst[e]);
    float c = g_dis[s] * g_dis[d];
    float4 v = *reinterpret_cast<const float4*>(&xw[(size_t)s * 64 + lane * 4]);
    v.x *= c; v.y *= c; v.z *= c; v.w *= c;
    red_add_v4(&g_agg2[(size_t)d * 64 + lane * 4], v);
}

// ---------------------------------------------------------------------------
// finalize: out = tau*prev + (1-tau)*leaky(agg + xw*dis^2 + bias)
// ---------------------------------------------------------------------------
__global__ void finalize_kernel(const float* __restrict__ agg,
                                const float* __restrict__ xw,
                                const float* __restrict__ prev,
                                const float* __restrict__ bias,
                                float* __restrict__ out,
                                int N, int H,
                                const int* __restrict__ ncur,
                                const int* __restrict__ nprev) {
    int idx = blockIdx.x * blockDim.x + threadIdx.x;
    int per = H >> 2;
    int total = N * per;
    if (idx >= total) return;
    int node = idx / per;
    int c4   = (idx - node * per) << 2;

    float np  = (float)(*nprev);
    float nc  = (float)(*ncur);
    float tau = np / (np + nc);
    float omt = 1.0f - tau;

    float d = g_dis[node];
    float selfc = d * d;

    size_t off = (size_t)node * H + c4;
    float4 av = *reinterpret_cast<const float4*>(&agg[off]);
    float4 xv = *reinterpret_cast<const float4*>(&xw[off]);
    float4 pv = *reinterpret_cast<const float4*>(&prev[off]);
    float4 bv = *reinterpret_cast<const float4*>(&bias[c4]);

    float4 o;
    float t;
    t = av.x + xv.x * selfc + bv.x; t = (t >= 0.f) ? t : LSLOPE * t; o.x = tau * pv.x + omt * t;
    t = av.y + xv.y * selfc + bv.y; t = (t >= 0.f) ? t : LSLOPE * t; o.y = tau * pv.y + omt * t;
    t = av.z + xv.z * selfc + bv.z; t = (t >= 0.f) ? t : LSLOPE * t; o.z = tau * pv.z + omt * t;
    t = av.w + xv.w * selfc + bv.w; t = (t >= 0.f) ? t : LSLOPE * t; o.w = tau * pv.w + omt * t;
    *reinterpret_cast<float4*>(&out[off]) = o;
}

// ---------------------------------------------------------------------------
// edge scoring: scores[e] = dot(emb2[a]*emb2[b], wsum) + bsum   (16 lanes/edge)
// ---------------------------------------------------------------------------
__global__ void score_kernel(const int* __restrict__ ea,
                             const int* __restrict__ eb,
                             const float* __restrict__ emb2,
                             float* __restrict__ scores, int EQ) {
    int gid  = blockIdx.x * blockDim.x + threadIdx.x;
    int e    = gid >> 4;
    if (e >= EQ) return;
    int lane = gid & 15;
    int s = __ldg(&ea[e]);
    int d = __ldg(&eb[e]);
    float4 vs = *reinterpret_cast<const float4*>(&emb2[(size_t)s * 64 + lane * 4]);
    float4 vd = *reinterpret_cast<const float4*>(&emb2[(size_t)d * 64 + lane * 4]);
    float4 w  = *reinterpret_cast<const float4*>(&g_wsum[lane * 4]);
    float p = vs.x * vd.x * w.x + vs.y * vd.y * w.y +
              vs.z * vd.z * w.z + vs.w * vd.w * w.w;
#pragma unroll
    for (int off = 8; off > 0; off >>= 1)
        p += __shfl_down_sync(0xffffffffu, p, off, 16);
    if (lane == 0) scores[e] = p + g_bsum[0];
}

// ---------------------------------------------------------------------------
// launch
// ---------------------------------------------------------------------------
static inline int cdiv(int a, int b) { return (a + b - 1) / b; }

extern "C" void kernel_launch(void* const* d_in, const int* in_sizes, int n_in,
                              void* d_out, int out_size) {
    const float* x      = (const float*)d_in[0];
    const int*   ei     = (const int*)  d_in[1];   // [2,E]
    const int*   eli    = (const int*)  d_in[2];   // [2,EQ]
    const float* prev1  = (const float*)d_in[3];
    const float* prev2  = (const float*)d_in[4];
    const float* W_pre1 = (const float*)d_in[5];
    const float* b_pre1 = (const float*)d_in[6];
    const float* W_pre2 = (const float*)d_in[7];
    const float* b_pre2 = (const float*)d_in[8];
    const float* W_c1   = (const float*)d_in[9];
    const float* b_c1   = (const float*)d_in[10];
    const float* W_c2   = (const float*)d_in[11];
    const float* b_c2   = (const float*)d_in[12];
    const float* W_post = (const float*)d_in[13];
    const float* b_post = (const float*)d_in[14];
    const int*   ncur   = (const int*)  d_in[15];
    const int*   nprev  = (const int*)  d_in[16];

    const int N  = in_sizes[0] / 128;
    const int E  = in_sizes[1] / 2;
    const int EQ = in_sizes[2] / 2;

    const int* e_src = ei;
    const int* e_dst = ei + E;
    const int* q_a   = eli;
    const int* q_b   = eli + EQ;

    float* out    = (float*)d_out;
    float* scores = out;
    float* emb1   = out + EQ;
    float* emb2   = out + EQ + (size_t)N * 128;

    // scratch symbol addresses
    float *p_h0, *p_h1, *p_xw1, *p_agg1, *p_xw2, *p_agg2;
    cudaGetSymbolAddress((void**)&p_h0,   g_h0);
    cudaGetSymbolAddress((void**)&p_h1,   g_h1);
    cudaGetSymbolAddress((void**)&p_xw1,  g_xw1);
    cudaGetSymbolAddress((void**)&p_agg1, g_agg1);
    cudaGetSymbolAddress((void**)&p_xw2,  g_xw2);
    cudaGetSymbolAddress((void**)&p_agg2, g_agg2);

    const int TB = 256;

    // 0) zero deg/agg, degree histogram, normalization, wsum
    init_kernel<<<cdiv(N * 128, TB), TB>>>(N);
    deg_kernel<<<cdiv(E, TB), TB>>>(e_dst, E);
    dis_kernel<<<cdiv(N, TB), TB>>>(N);
    wsum_kernel<<<1, 64>>>(W_post, b_post);

    // 1) preprocess MLP
    {
        dim3 g(256 / 64, cdiv(N, 128));
        gemm_kernel<true, true><<<g, TB>>>(x, W_pre1, b_pre1, p_h0, N, 256, 128);
    }
    {
        dim3 g(128 / 64, cdiv(N, 128));
        gemm_kernel<true, true><<<g, TB>>>(p_h0, W_pre2, b_pre2, p_h1, N, 128, 256);
    }

    // 2) GCN layer 1
    {
        dim3 g(128 / 64, cdiv(N, 128));
        gemm_kernel<false, false><<<g, TB>>>(p_h1, W_c1, nullptr, p_xw1, N, 128, 128);
    }
    scatter128_kernel<<<cdiv(E * 32, TB), TB>>>(e_src, e_dst, p_xw1, E);
    finalize_kernel<<<cdiv(N * 32, TB), TB>>>(p_agg1, p_xw1, prev1, b_c1, emb1,
                                              N, 128, ncur, nprev);

    // 3) GCN layer 2
    {
        dim3 g(64 / 64, cdiv(N, 128));
        gemm_kernel<false, false><<<g, TB>>>(emb1, W_c2, nullptr, p_xw2, N, 64, 128);
    }
    scatter64_kernel<<<cdiv(E * 16, TB), TB>>>(e_src, e_dst, p_xw2, E);
    finalize_kernel<<<cdiv(N * 16, TB), TB>>>(p_agg2, p_xw2, prev2, b_c2, emb2,
                                              N, 64, ncur, nprev);

    // 4) edge scoring
    score_kernel<<<cdiv(EQ * 16, TB), TB>>>(q_a, q_b, emb2, scores, EQ);
}

// round 2
// speedup vs baseline: 1.0512x; 1.0512x over previous
#include <cuda_runtime.h>
#include <cstdint>

// ---------------------------------------------------------------------------
// EdgeRolandGNN: MLP (2x GEMM+leaky) -> GCN1 -> blend -> GCN2 -> blend ->
// edge scoring.  GEMMs via mma.sync tf32 tensor cores.
// ---------------------------------------------------------------------------

#define LSLOPE 0.01f

static constexpr int MAXN = 50000;

// Scratch (device globals; no allocation allowed)
__device__ float g_h0 [MAXN * 256];   // after MLP layer 1
__device__ float g_h1 [MAXN * 128];   // after MLP layer 2
__device__ float g_xw1[MAXN * 128];   // h1 @ W_c1
__device__ float g_agg1[MAXN * 128];
__device__ float g_xw2[MAXN * 64];    // emb1 @ W_c2
__device__ float g_agg2[MAXN * 64];
__device__ float g_dis [MAXN];
__device__ int   g_deg [MAXN];
__device__ float g_wsum[64];
__device__ float g_bsum[1];

// ---------------------------------------------------------------------------
__global__ void init_kernel(int N) {
    int idx = blockIdx.x * blockDim.x + threadIdx.x;
    int n128 = N * 128;
    int n64  = N * 64;
    if (idx < n128) g_agg1[idx] = 0.0f;
    if (idx < n64)  g_agg2[idx] = 0.0f;
    if (idx < N)    g_deg[idx]  = 0;
}

__global__ void deg_kernel(const int* __restrict__ dst, int E) {
    int e = blockIdx.x * blockDim.x + threadIdx.x;
    if (e < E) atomicAdd(&g_deg[dst[e]], 1);
}

__global__ void dis_kernel(int N) {
    int i = blockIdx.x * blockDim.x + threadIdx.x;
    if (i < N) g_dis[i] = rsqrtf((float)g_deg[i] + 1.0f);
}

__global__ void wsum_kernel(const float* __restrict__ W_post,
                            const float* __restrict__ b_post) {
    int i = threadIdx.x;
    if (i < 64) g_wsum[i] = W_post[2 * i] + W_post[2 * i + 1];
    if (i == 0) g_bsum[0] = b_post[0] + b_post[1];
}

// ---------------------------------------------------------------------------
// tf32 helpers
// ---------------------------------------------------------------------------
__device__ __forceinline__ unsigned f2tf32(float f) {
    unsigned r;
    asm("cvt.rna.tf32.f32 %0, %1;" : "=r"(r) : "f"(f));
    return r;
}

__device__ __forceinline__ void mma_tf32(float* c, const unsigned* a,
                                         const unsigned* b) {
    asm volatile(
        "mma.sync.aligned.m16n8k8.row.col.f32.tf32.tf32.f32 "
        "{%0,%1,%2,%3}, {%4,%5,%6,%7}, {%8,%9}, {%0,%1,%2,%3};"
        : "+f"(c[0]), "+f"(c[1]), "+f"(c[2]), "+f"(c[3])
        : "r"(a[0]), "r"(a[1]), "r"(a[2]), "r"(a[3]),
          "r"(b[0]), "r"(b[1]));
}

// ---------------------------------------------------------------------------
// Tensor-core GEMM: C[M,N] = act(A[M,K] @ B[K,N] + bias)
// BM=128, BN=64, BK=32, 4 warps (128 threads), warp tile 64x32.
// Fragment-shuffled smem: A-frag = 1x lds.128, B-frag = 1x lds.64 per tile.
// Requires K % 32 == 0, N % 64 == 0.
// ---------------------------------------------------------------------------
template <bool BIAS, bool ACT>
__global__ __launch_bounds__(128)
void gemm_tf32(const float* __restrict__ A, const float* __restrict__ B,
               const float* __restrict__ bias, float* __restrict__ C,
               int M, int N, int K) {
    constexpr int BM = 128, BN = 64, BK = 32;

    // As: [mt(8)][kt(4)][lane(32)][slot(4)]  -> 4096 u32 = 16 KB
    // Bs: [kt(4)][nt(8)][lane(32)][slot(2)]  -> 2048 u32 =  8 KB
    __shared__ __align__(16) unsigned As[8 * 4 * 32 * 4];
    __shared__ __align__(16) unsigned Bs[4 * 8 * 32 * 2];

    const int tid  = threadIdx.x;
    const int lane = tid & 31;
    const int wid  = tid >> 5;
    const int wm   = wid >> 1;   // 0..1 : m-offset wm*64 (m-tiles wm*4..+3)
    const int wn   = wid & 1;    // 0..1 : n-offset wn*32 (n-tiles wn*4..+3)
    const int bm   = blockIdx.y * BM;
    const int bn   = blockIdx.x * BN;

    float acc[4][4][4];
#pragma unroll
    for (int mt = 0; mt < 4; mt++)
#pragma unroll
        for (int nt = 0; nt < 4; nt++)
#pragma unroll
            for (int i = 0; i < 4; i++) acc[mt][nt][i] = 0.0f;

    float4 ra[8];   // A staging: 8 float4/thread  (128x32 tile)
    float4 rb[4];   // B staging: 4 float4/thread  (32x64 tile)

    auto loadA = [&](int k0) {
#pragma unroll
        for (int t = 0; t < 8; t++) {
            int idx = tid + t * 128;
            int row = idx >> 3;
            int c4  = (idx & 7) << 2;
            int gr  = bm + row;
            ra[t] = (gr < M)
                  ? *reinterpret_cast<const float4*>(&A[(size_t)gr * K + k0 + c4])
                  : make_float4(0.f, 0.f, 0.f, 0.f);
        }
    };
    auto loadB = [&](int k0) {
#pragma unroll
        for (int t = 0; t < 4; t++) {
            int idx = tid + t * 128;
            int row = idx >> 4;
            int c4  = (idx & 15) << 2;
            rb[t] = *reinterpret_cast<const float4*>(&B[(size_t)(k0 + row) * N + bn + c4]);
        }
    };
    auto storeA = [&]() {
#pragma unroll
        for (int t = 0; t < 8; t++) {
            int idx = tid + t * 128;
            int row = idx >> 3;          // m_local
            int c4  = (idx & 7) << 2;    // k_local base
            int r   = row & 15;
            int mt  = row >> 4;
            float v[4] = {ra[t].x, ra[t].y, ra[t].z, ra[t].w};
#pragma unroll
            for (int j = 0; j < 4; j++) {
                int k    = c4 + j;
                int kt   = k >> 3;
                int c    = k & 7;
                int ln   = ((r & 7) << 2) | (c & 3);
                int slot = (r >> 3) | ((c >> 2) << 1);
                As[(((mt * 4 + kt) * 32) + ln) * 4 + slot] = f2tf32(v[j]);
            }
        }
    };
    auto storeB = [&]() {
#pragma unroll
        for (int t = 0; t < 4; t++) {
            int idx = tid + t * 128;
            int k   = idx >> 4;          // k_local
            int c4  = (idx & 15) << 2;   // n_local base
            int kt  = k >> 3;
            int kr  = k & 7;
            float v[4] = {rb[t].x, rb[t].y, rb[t].z, rb[t].w};
#pragma unroll
            for (int j = 0; j < 4; j++) {
                int n    = c4 + j;
                int nt   = n >> 3;
                int nc   = n & 7;
                int ln   = (nc << 2) | (kr & 3);
                int slot = kr >> 2;
                Bs[(((kt * 8 + nt) * 32) + ln) * 2 + slot] = f2tf32(v[j]);
            }
        }
    };

    const int T = K / BK;
    loadA(0); loadB(0);
    storeA(); storeB();

    for (int it = 0; it < T; ++it) {
        __syncthreads();
        bool more = (it + 1) < T;
        if (more) { loadA((it + 1) * BK); loadB((it + 1) * BK); }

#pragma unroll
        for (int ks = 0; ks < 4; ks++) {
            unsigned af[4][4];
            unsigned bf[4][2];
#pragma unroll
            for (int mt = 0; mt < 4; mt++) {
                uint4 v = *reinterpret_cast<const uint4*>(
                    &As[(((wm * 4 + mt) * 4 + ks) * 32 + lane) * 4]);
                af[mt][0] = v.x; af[mt][1] = v.y; af[mt][2] = v.z; af[mt][3] = v.w;
            }
#pragma unroll
            for (int nt = 0; nt < 4; nt++) {
                uint2 v = *reinterpret_cast<const uint2*>(
                    &Bs[((ks * 8 + wn * 4 + nt) * 32 + lane) * 2]);
                bf[nt][0] = v.x; bf[nt][1] = v.y;
            }
#pragma unroll
            for (int mt = 0; mt < 4; mt++)
#pragma unroll
                for (int nt = 0; nt < 4; nt++)
                    mma_tf32(acc[mt][nt], af[mt], bf[nt]);
        }

        if (more) { __syncthreads(); storeA(); storeB(); }
    }

    // epilogue: c0,c1 at (row g, col 2t), c2,c3 at (row g+8, col 2t)
    const int g = lane >> 2;
    const int t = lane & 3;
#pragma unroll
    for (int nt = 0; nt < 4; nt++) {
        int col = bn + wn * 32 + nt * 8 + 2 * t;
        float b0 = 0.f, b1 = 0.f;
        if (BIAS) { b0 = bias[col]; b1 = bias[col + 1]; }
#pragma unroll
        for (int mt = 0; mt < 4; mt++) {
            int row0 = bm + wm * 64 + mt * 16 + g;
            float v0 = acc[mt][nt][0] + b0;
            float v1 = acc[mt][nt][1] + b1;
            float v2 = acc[mt][nt][2] + b0;
            float v3 = acc[mt][nt][3] + b1;
            if (ACT) {
                v0 = (v0 >= 0.f) ? v0 : LSLOPE * v0;
                v1 = (v1 >= 0.f) ? v1 : LSLOPE * v1;
                v2 = (v2 >= 0.f) ? v2 : LSLOPE * v2;
                v3 = (v3 >= 0.f) ? v3 : LSLOPE * v3;
            }
            if (row0 < M)
                *reinterpret_cast<float2*>(&C[(size_t)row0 * N + col]) =
                    make_float2(v0, v1);
            if (row0 + 8 < M)
                *reinterpret_cast<float2*>(&C[(size_t)(row0 + 8) * N + col]) =
                    make_float2(v2, v3);
        }
    }
}

// ---------------------------------------------------------------------------
// Edge scatter: agg[dst] += xw[src] * dis[src]*dis[dst], via red.global.v4.f32
// ---------------------------------------------------------------------------
__device__ __forceinline__ void red_add_v4(float* p, float4 v) {
    unsigned long long a = (unsigned long long)__cvta_generic_to_global(p);
    asm volatile("red.global.add.v4.f32 [%0], {%1, %2, %3, %4};"
                 :: "l"(a), "f"(v.x), "f"(v.y), "f"(v.z), "f"(v.w)
                 : "memory");
}

__global__ void scatter128_kernel(const int* __restrict__ src,
                                  const int* __restrict__ dst,
                                  const float* __restrict__ xw, int E) {
    int gid  = blockIdx.x * blockDim.x + threadIdx.x;
    int e    = gid >> 5;
    if (e >= E) return;
    int lane = gid & 31;
    int s = __ldg(&src[e]);
    int d = __ldg(&dst[e]);
    float c = g_dis[s] * g_dis[d];
    float4 v = *reinterpret_cast<const float4*>(&xw[(size_t)s * 128 + lane * 4]);
    v.x *= c; v.y *= c; v.z *= c; v.w *= c;
    red_add_v4(&g_agg1[(size_t)d * 128 + lane * 4], v);
}

__global__ void scatter64_kernel(const int* __restrict__ src,
                                 const int* __restrict__ dst,
                                 const float* __restrict__ xw, int E) {
    int gid  = blockIdx.x * blockDim.x + threadIdx.x;
    int e    = gid >> 4;
    if (e >= E) return;
    int lane = gid & 15;
    int s = __ldg(&src[e]);
    int d = __ldg(&dst[e]);
    float c = g_dis[s] * g_dis[d];
    float4 v = *reinterpret_cast<const float4*>(&xw[(size_t)s * 64 + lane * 4]);
    v.x *= c; v.y *= c; v.z *= c; v.w *= c;
    red_add_v4(&g_agg2[(size_t)d * 64 + lane * 4], v);
}

// ---------------------------------------------------------------------------
// finalize: out = tau*prev + (1-tau)*leaky(agg + xw*dis^2 + bias)
// ---------------------------------------------------------------------------
__global__ void finalize_kernel(const float* __restrict__ agg,
                                const float* __restrict__ xw,
                                const float* __restrict__ prev,
                                const float* __restrict__ bias,
                                float* __restrict__ out,
                                int N, int H,
                                const int* __restrict__ ncur,
                                const int* __restrict__ nprev) {
    int idx = blockIdx.x * blockDim.x + threadIdx.x;
    int per = H >> 2;
    int total = N * per;
    if (idx >= total) return;
    int node = idx / per;
    int c4   = (idx - node * per) << 2;

    float np  = (float)(*nprev);
    float nc  = (float)(*ncur);
    float tau = np / (np + nc);
    float omt = 1.0f - tau;

    float d = g_dis[node];
    float selfc = d * d;

    size_t off = (size_t)node * H + c4;
    float4 av = *reinterpret_cast<const float4*>(&agg[off]);
    float4 xv = *reinterpret_cast<const float4*>(&xw[off]);
    float4 pv = *reinterpret_cast<const float4*>(&prev[off]);
    float4 bv = *reinterpret_cast<const float4*>(&bias[c4]);

    float4 o;
    float t;
    t = av.x + xv.x * selfc + bv.x; t = (t >= 0.f) ? t : LSLOPE * t; o.x = tau * pv.x + omt * t;
    t = av.y + xv.y * selfc + bv.y; t = (t >= 0.f) ? t : LSLOPE * t; o.y = tau * pv.y + omt * t;
    t = av.z + xv.z * selfc + bv.z; t = (t >= 0.f) ? t : LSLOPE * t; o.z = tau * pv.z + omt * t;
    t = av.w + xv.w * selfc + bv.w; t = (t >= 0.f) ? t : LSLOPE * t; o.w = tau * pv.w + omt * t;
    *reinterpret_cast<float4*>(&out[off]) = o;
}

// ---------------------------------------------------------------------------
// edge scoring: scores[e] = dot(emb2[a]*emb2[b], wsum) + bsum   (16 lanes/edge)
// ---------------------------------------------------------------------------
__global__ void score_kernel(const int* __restrict__ ea,
                             const int* __restrict__ eb,
                             const float* __restrict__ emb2,
                             float* __restrict__ scores, int EQ) {
    int gid  = blockIdx.x * blockDim.x + threadIdx.x;
    int e    = gid >> 4;
    if (e >= EQ) return;
    int lane = gid & 15;
    int s = __ldg(&ea[e]);
    int d = __ldg(&eb[e]);
    float4 vs = *reinterpret_cast<const float4*>(&emb2[(size_t)s * 64 + lane * 4]);
    float4 vd = *reinterpret_cast<const float4*>(&emb2[(size_t)d * 64 + lane * 4]);
    float4 w  = *reinterpret_cast<const float4*>(&g_wsum[lane * 4]);
    float p = vs.x * vd.x * w.x + vs.y * vd.y * w.y +
              vs.z * vd.z * w.z + vs.w * vd.w * w.w;
#pragma unroll
    for (int off = 8; off > 0; off >>= 1)
        p += __shfl_down_sync(0xffffffffu, p, off, 16);
    if (lane == 0) scores[e] = p + g_bsum[0];
}

// ---------------------------------------------------------------------------
// launch
// ---------------------------------------------------------------------------
static inline int cdiv(int a, int b) { return (a + b - 1) / b; }

extern "C" void kernel_launch(void* const* d_in, const int* in_sizes, int n_in,
                              void* d_out, int out_size) {
    const float* x      = (const float*)d_in[0];
    const int*   ei     = (const int*)  d_in[1];   // [2,E]
    const int*   eli    = (const int*)  d_in[2];   // [2,EQ]
    const float* prev1  = (const float*)d_in[3];
    const float* prev2  = (const float*)d_in[4];
    const float* W_pre1 = (const float*)d_in[5];
    const float* b_pre1 = (const float*)d_in[6];
    const float* W_pre2 = (const float*)d_in[7];
    const float* b_pre2 = (const float*)d_in[8];
    const float* W_c1   = (const float*)d_in[9];
    const float* b_c1   = (const float*)d_in[10];
    const float* W_c2   = (const float*)d_in[11];
    const float* b_c2   = (const float*)d_in[12];
    const float* W_post = (const float*)d_in[13];
    const float* b_post = (const float*)d_in[14];
    const int*   ncur   = (const int*)  d_in[15];
    const int*   nprev  = (const int*)  d_in[16];

    const int Nn = in_sizes[0] / 128;
    const int E  = in_sizes[1] / 2;
    const int EQ = in_sizes[2] / 2;

    const int* e_src = ei;
    const int* e_dst = ei + E;
    const int* q_a   = eli;
    const int* q_b   = eli + EQ;

    float* out    = (float*)d_out;
    float* scores = out;
    float* emb1   = out + EQ;
    float* emb2   = out + EQ + (size_t)Nn * 128;

    float *p_h0, *p_h1, *p_xw1, *p_agg1, *p_xw2, *p_agg2;
    cudaGetSymbolAddress((void**)&p_h0,   g_h0);
    cudaGetSymbolAddress((void**)&p_h1,   g_h1);
    cudaGetSymbolAddress((void**)&p_xw1,  g_xw1);
    cudaGetSymbolAddress((void**)&p_agg1, g_agg1);
    cudaGetSymbolAddress((void**)&p_xw2,  g_xw2);
    cudaGetSymbolAddress((void**)&p_agg2, g_agg2);

    const int TB = 256;
    const int MB = cdiv(Nn, 128);

    // 0) zero deg/agg, degree histogram, normalization, wsum
    init_kernel<<<cdiv(Nn * 128, TB), TB>>>(Nn);
    deg_kernel<<<cdiv(E, TB), TB>>>(e_dst, E);
    dis_kernel<<<cdiv(Nn, TB), TB>>>(Nn);
    wsum_kernel<<<1, 64>>>(W_post, b_post);

    // 1) preprocess MLP
    gemm_tf32<true, true><<<dim3(4, MB), 128>>>(x,    W_pre1, b_pre1, p_h0, Nn, 256, 128);
    gemm_tf32<true, true><<<dim3(2, MB), 128>>>(p_h0, W_pre2, b_pre2, p_h1, Nn, 128, 256);

    // 2) GCN layer 1
    gemm_tf32<false, false><<<dim3(2, MB), 128>>>(p_h1, W_c1, nullptr, p_xw1, Nn, 128, 128);
    scatter128_kernel<<<cdiv(E * 32, TB), TB>>>(e_src, e_dst, p_xw1, E);
    finalize_kernel<<<cdiv(Nn * 32, TB), TB>>>(p_agg1, p_xw1, prev1, b_c1, emb1,
                                               Nn, 128, ncur, nprev);

    // 3) GCN layer 2
    gemm_tf32<false, false><<<dim3(1, MB), 128>>>(emb1, W_c2, nullptr, p_xw2, Nn, 64, 128);
    scatter64_kernel<<<cdiv(E * 16, TB), TB>>>(e_src, e_dst, p_xw2, E);
    finalize_kernel<<<cdiv(Nn * 16, TB), TB>>>(p_agg2, p_xw2, prev2, b_c2, emb2,
                                               Nn, 64, ncur, nprev);

    // 4) edge scoring
    score_kernel<<<cdiv(EQ * 16, TB), TB>>>(q_a, q_b, emb2, scores, EQ);
}